// round 3
// baseline (speedup 1.0000x reference)
#include <cuda_runtime.h>
#include <math.h>
#include <stdint.h>

// ---------------------------------------------------------------------------
// Shapes
// ---------------------------------------------------------------------------
#define BATCH  8192
#define DIN    4096
#define DMODEL 512
#define FDIM   2048
#define NH     3
#define HD     256
#define OUTD   896

// GEMM tile config
#define BM 128
#define BN 128
#define BK 32
#define THREADS 128
#define STAGES 3
#define STAGE_FLOATS (2 * BM * BK)            // A tile + B tile per stage
#define SMB (STAGES * STAGE_FLOATS * 4)       // 96 KB

// Epilogue flags
#define F_B2   1
#define F_GELU 2
#define F_RES  4

// ---------------------------------------------------------------------------
// Scratch
// ---------------------------------------------------------------------------
__device__ float g_h  [BATCH * DMODEL];
__device__ float g_hb [BATCH * DMODEL];
__device__ float g_t  [BATCH * DMODEL];
__device__ float g_u  [BATCH * DMODEL];
__device__ float g_ff [BATCH * FDIM];
__device__ float g_z  [BATCH * NH * HD];

// transposed + tf32-rounded + pair-packed weights [N][K]
__device__ float g_wt_in [DMODEL * DIN];
__device__ float g_wt_vsa[DMODEL * DMODEL];
__device__ float g_wt_osa[DMODEL * DMODEL];
__device__ float g_wt_vca[DMODEL * DMODEL];
__device__ float g_wt_oca[DMODEL * DMODEL];
__device__ float g_wt_ff1[FDIM * DMODEL];
__device__ float g_wt_ff2[DMODEL * FDIM];
__device__ float g_wt_h1 [NH * HD * DMODEL];
__device__ float g_wt_h2 [NH * OUTD * HD];

// ---------------------------------------------------------------------------
// Helpers
// ---------------------------------------------------------------------------
static __device__ __forceinline__ void cp16(float* sm, const float* gm) {
    unsigned s = (unsigned)__cvta_generic_to_shared(sm);
    asm volatile("cp.async.ca.shared.global [%0], [%1], 16;\n" :: "r"(s), "l"(gm));
}
static __device__ __forceinline__ unsigned f2tf32(float f) {
    unsigned u;
    asm("cvt.rna.tf32.f32 %0, %1;" : "=r"(u) : "f"(f));
    return u;
}
static __device__ __forceinline__ float gelu_exact(float v) {
    return 0.5f * v * (1.0f + erff(v * 0.70710678118654752f));
}

// ---------------------------------------------------------------------------
// tf32 GEMM via mma.sync m16n8k8, 64x64 warp tiles, packed-B, zero-CVT loop.
// A row-major [M,K] (fp32, converted at staging).
// B = pre-transposed, tf32-rounded, pair-packed weights [N][K].
// grid (N/BN, M/BM, z). 128 threads.
// ---------------------------------------------------------------------------
template<int FLAGS>
__global__ void __launch_bounds__(THREADS, 2) gemm_tc(
    const float* __restrict__ A, int lda, long sA,
    const float* __restrict__ B, long sB,
    float* __restrict__ C, int ldc, long sC,
    int K,
    const float* __restrict__ bias, int sBias,
    const float* __restrict__ bias2,
    const float* __restrict__ res)
{
    extern __shared__ float sm[];
    const int tid  = threadIdx.x;
    const int lane = tid & 31;
    const int warp = tid >> 5;           // 0..3
    const int z = blockIdx.z;
    A    += (long)z * sA;
    B    += (long)z * sB;
    C    += (long)z * sC;
    bias += (long)z * sBias;
    const float* resb = (FLAGS & F_RES) ? (res + (long)z * sC) : nullptr;

    const long mBase = (long)blockIdx.y * BM;
    const int  nBase = blockIdx.x * BN;
    const float* Ag = A + mBase * lda;
    const float* Bg = B + (long)nBase * K;

    const int r0 = lane & 7;       // staging row-in-8
    const int cg = lane >> 3;      // staging chunk group 0..3
    const int numK = K / BK;

    float4 fA[8];
    auto ldgA = [&](int kt) {
#pragma unroll
        for (int j = 0; j < 4; j++)
#pragma unroll
            for (int m = 0; m < 2; m++) {
                int row = r0 + 8 * warp + 32 * j;
                int chunk = cg * 2 + m;
                fA[j * 2 + m] = *(const float4*)(Ag + (long)row * lda + kt * BK + chunk * 4);
            }
    };
    auto stsA = [&](int stg) {
        float* As = sm + stg * STAGE_FLOATS;
#pragma unroll
        for (int j = 0; j < 4; j++)
#pragma unroll
            for (int m = 0; m < 2; m++) {
                int row = r0 + 8 * warp + 32 * j;
                int chunk = cg * 2 + m;
                float4 v = fA[j * 2 + m];
                uint4 o = make_uint4(f2tf32(v.x), f2tf32(v.y), f2tf32(v.z), f2tf32(v.w));
                *(uint4*)(As + row * 32 + ((chunk ^ r0) * 4)) = o;
            }
    };
    auto cpB = [&](int kt, int stg) {
        float* Bs = sm + stg * STAGE_FLOATS + BM * BK;
#pragma unroll
        for (int j = 0; j < 4; j++)
#pragma unroll
            for (int m = 0; m < 2; m++) {
                int row = r0 + 8 * warp + 32 * j;
                int chunk = cg * 2 + m;
                cp16(Bs + row * 32 + ((chunk ^ r0) * 4),
                     Bg + (long)row * K + kt * BK + chunk * 4);
            }
    };

    float acc[4][8][4];
#pragma unroll
    for (int a = 0; a < 4; a++)
#pragma unroll
        for (int b = 0; b < 8; b++)
#pragma unroll
            for (int c = 0; c < 4; c++) acc[a][b][c] = 0.f;

    const int wm = warp >> 1, wn = warp & 1;      // 2x2 warp grid of 64x64 tiles
    const int q  = lane >> 2, cc = lane & 3;

    // ---- prologue ----
    ldgA(0); stsA(0); cpB(0, 0);
    asm volatile("cp.async.commit_group;\n" ::: "memory");
    if (numK > 1) { ldgA(1); cpB(1, 1); }
    asm volatile("cp.async.commit_group;\n" ::: "memory");

    for (int kt = 0; kt < numK; kt++) {
        asm volatile("cp.async.wait_group 1;\n" ::: "memory");
        __syncthreads();

        if (kt + 1 < numK) stsA((kt + 1) % STAGES);
        if (kt + 2 < numK) { ldgA(kt + 2); cpB(kt + 2, (kt + 2) % STAGES); }
        asm volatile("cp.async.commit_group;\n" ::: "memory");

        const float* As = sm + (kt % STAGES) * STAGE_FLOATS;
        const float* Bs = As + BM * BK;

#pragma unroll
        for (int ks = 0; ks < 4; ks++) {
            uint32_t af[4][4];
#pragma unroll
            for (int mi = 0; mi < 4; mi++) {
                const float* ab = As + (wm * 64 + mi * 16 + q) * 32;
                int ch0 = (2 * ks) ^ q, ch1 = (2 * ks + 1) ^ q;
                af[mi][0] = __float_as_uint(ab[ch0 * 4 + cc]);
                af[mi][1] = __float_as_uint(ab[8 * 32 + ch0 * 4 + cc]);
                af[mi][2] = __float_as_uint(ab[ch1 * 4 + cc]);
                af[mi][3] = __float_as_uint(ab[8 * 32 + ch1 * 4 + cc]);
            }
            uint32_t bf[8][2];
#pragma unroll
            for (int ni = 0; ni < 8; ni++) {
                const float* nb = Bs + (wn * 64 + ni * 8 + q) * 32;
                int j = 2 * ks + (cc >> 1);
                uint2 bv = *(const uint2*)(nb + ((j ^ q) * 4) + (cc & 1) * 2);
                bf[ni][0] = bv.x; bf[ni][1] = bv.y;
            }
#pragma unroll
            for (int mi = 0; mi < 4; mi++)
#pragma unroll
                for (int ni = 0; ni < 8; ni++)
                    asm volatile(
                        "mma.sync.aligned.m16n8k8.row.col.f32.tf32.tf32.f32 "
                        "{%0,%1,%2,%3},{%4,%5,%6,%7},{%8,%9},{%0,%1,%2,%3};\n"
                        : "+f"(acc[mi][ni][0]), "+f"(acc[mi][ni][1]),
                          "+f"(acc[mi][ni][2]), "+f"(acc[mi][ni][3])
                        : "r"(af[mi][0]), "r"(af[mi][1]), "r"(af[mi][2]), "r"(af[mi][3]),
                          "r"(bf[ni][0]), "r"(bf[ni][1]));
        }
    }

    // ---- fused epilogue ----
#pragma unroll
    for (int mi = 0; mi < 4; mi++) {
#pragma unroll
        for (int ni = 0; ni < 8; ni++) {
            int col = nBase + wn * 64 + ni * 8 + cc * 2;
            float b0 = bias[col], b1 = bias[col + 1];
            if (FLAGS & F_B2) { b0 += bias2[col]; b1 += bias2[col + 1]; }
#pragma unroll
            for (int h = 0; h < 2; h++) {
                long row = mBase + wm * 64 + mi * 16 + q + 8 * h;
                float v0 = acc[mi][ni][2 * h + 0] + b0;
                float v1 = acc[mi][ni][2 * h + 1] + b1;
                if (FLAGS & F_GELU) { v0 = gelu_exact(v0); v1 = gelu_exact(v1); }
                long idx = row * ldc + col;
                if (FLAGS & F_RES) {
                    float2 rr = *(const float2*)(resb + idx);
                    v0 += rr.x; v1 += rr.y;
                }
                *(float2*)(C + idx) = make_float2(v0, v1);
            }
        }
    }
}

// ---------------------------------------------------------------------------
// Weight transpose + tf32 round + pair-pack: out[n][pack(k)] = tf32(in[k][n]).
// pack: within each 8-k group, (k -> (k&3)*2 + ((k>>2)&1)) so that fragment
// pairs (k, k+4) are adjacent (LDS.64 in the GEMM inner loop).
// ---------------------------------------------------------------------------
__global__ void tp_kernel(const float* __restrict__ in, float* __restrict__ out,
                          int K, int N)
{
    __shared__ float t[32][33];
    const long zo = (long)blockIdx.z * K * N;
    const int k0 = blockIdx.x * 32, n0 = blockIdx.y * 32;
    const int tx = threadIdx.x, ty = threadIdx.y;
#pragma unroll
    for (int i = 0; i < 32; i += 8)
        t[ty + i][tx] = in[zo + (long)(k0 + ty + i) * N + n0 + tx];
    __syncthreads();
#pragma unroll
    for (int i = 0; i < 32; i += 8) {
        int n = n0 + ty + i;
        int k = k0 + tx;
        int kp = (k & ~7) + ((k & 3) * 2) + ((k >> 2) & 1);
        out[zo + (long)n * K + kp] = __uint_as_float(f2tf32(t[tx][ty + i]));
    }
}

// ---------------------------------------------------------------------------
// Row LayerNorm
// ---------------------------------------------------------------------------
__global__ void ln_kernel(const float* __restrict__ in, float* __restrict__ out,
                          const float* __restrict__ g, const float* __restrict__ b,
                          int C, int headMod)
{
    __shared__ float red[8];
    const int row = blockIdx.x;
    const float* x = in + (long)row * C;
    float* y = out + (long)row * C;
    const int go = headMod ? (row % headMod) * C : 0;

    float s = 0.f, s2 = 0.f;
    for (int i = threadIdx.x; i < C; i += 128) {
        float v = x[i]; s += v; s2 += v * v;
    }
#pragma unroll
    for (int o = 16; o; o >>= 1) {
        s  += __shfl_xor_sync(0xffffffffu, s, o);
        s2 += __shfl_xor_sync(0xffffffffu, s2, o);
    }
    const int w = threadIdx.x >> 5;
    if ((threadIdx.x & 31) == 0) { red[w] = s; red[4 + w] = s2; }
    __syncthreads();
    if (threadIdx.x == 0) {
        float ts = 0.f, ts2 = 0.f;
#pragma unroll
        for (int i = 0; i < 4; i++) { ts += red[i]; ts2 += red[4 + i]; }
        red[0] = ts; red[4] = ts2;
    }
    __syncthreads();
    const float mean = red[0] / C;
    const float var  = red[4] / C - mean * mean;
    const float inv  = rsqrtf(var + 1e-5f);
    for (int i = threadIdx.x; i < C; i += 128)
        y[i] = (x[i] - mean) * inv * g[go + i] + b[go + i];
}

// ---------------------------------------------------------------------------
// Launch
// ---------------------------------------------------------------------------
extern "C" void kernel_launch(void* const* d_in, const int* in_sizes, int n_in,
                              void* d_out, int out_size)
{
    const float* x      = (const float*)d_in[0];
    const float* w_in   = (const float*)d_in[1];
    const float* b_in   = (const float*)d_in[2];
    const float* pos    = (const float*)d_in[3];
    const float* ln1_g  = (const float*)d_in[4];
    const float* ln1_b  = (const float*)d_in[5];
    const float* wv_sa  = (const float*)d_in[6];
    const float* bv_sa  = (const float*)d_in[7];
    const float* wo_sa  = (const float*)d_in[8];
    const float* bo_sa  = (const float*)d_in[9];
    const float* wv_ca  = (const float*)d_in[12];
    const float* bv_ca  = (const float*)d_in[13];
    const float* wo_ca  = (const float*)d_in[14];
    const float* bo_ca  = (const float*)d_in[15];
    const float* ln3_g  = (const float*)d_in[16];
    const float* ln3_b  = (const float*)d_in[17];
    const float* w_ff1  = (const float*)d_in[18];
    const float* b_ff1  = (const float*)d_in[19];
    const float* w_ff2  = (const float*)d_in[20];
    const float* b_ff2  = (const float*)d_in[21];
    const float* lnout_g= (const float*)d_in[22];
    const float* lnout_b= (const float*)d_in[23];
    const float* wh1    = (const float*)d_in[24];
    const float* bh1    = (const float*)d_in[25];
    const float* lnh_g  = (const float*)d_in[26];
    const float* lnh_b  = (const float*)d_in[27];
    const float* wh2    = (const float*)d_in[28];
    const float* bh2    = (const float*)d_in[29];
    float* out = (float*)d_out;

    float *h, *hb, *t, *u, *ff, *zz;
    float *wt_in, *wt_vsa, *wt_osa, *wt_vca, *wt_oca, *wt_ff1, *wt_ff2, *wt_h1, *wt_h2;
    cudaGetSymbolAddress((void**)&h,  g_h);
    cudaGetSymbolAddress((void**)&hb, g_hb);
    cudaGetSymbolAddress((void**)&t,  g_t);
    cudaGetSymbolAddress((void**)&u,  g_u);
    cudaGetSymbolAddress((void**)&ff, g_ff);
    cudaGetSymbolAddress((void**)&zz, g_z);
    cudaGetSymbolAddress((void**)&wt_in,  g_wt_in);
    cudaGetSymbolAddress((void**)&wt_vsa, g_wt_vsa);
    cudaGetSymbolAddress((void**)&wt_osa, g_wt_osa);
    cudaGetSymbolAddress((void**)&wt_vca, g_wt_vca);
    cudaGetSymbolAddress((void**)&wt_oca, g_wt_oca);
    cudaGetSymbolAddress((void**)&wt_ff1, g_wt_ff1);
    cudaGetSymbolAddress((void**)&wt_ff2, g_wt_ff2);
    cudaGetSymbolAddress((void**)&wt_h1,  g_wt_h1);
    cudaGetSymbolAddress((void**)&wt_h2,  g_wt_h2);

    cudaFuncSetAttribute(gemm_tc<F_B2>,   cudaFuncAttributeMaxDynamicSharedMemorySize, SMB);
    cudaFuncSetAttribute(gemm_tc<0>,      cudaFuncAttributeMaxDynamicSharedMemorySize, SMB);
    cudaFuncSetAttribute(gemm_tc<F_RES>,  cudaFuncAttributeMaxDynamicSharedMemorySize, SMB);
    cudaFuncSetAttribute(gemm_tc<F_GELU>, cudaFuncAttributeMaxDynamicSharedMemorySize, SMB);

    dim3 tb(32, 8);
    // weight transposes -> [N][K], tf32-rounded, pair-packed
    tp_kernel<<<dim3(DIN / 32, DMODEL / 32, 1), tb>>>(w_in,  wt_in,  DIN, DMODEL);
    tp_kernel<<<dim3(DMODEL / 32, DMODEL / 32, 1), tb>>>(wv_sa, wt_vsa, DMODEL, DMODEL);
    tp_kernel<<<dim3(DMODEL / 32, DMODEL / 32, 1), tb>>>(wo_sa, wt_osa, DMODEL, DMODEL);
    tp_kernel<<<dim3(DMODEL / 32, DMODEL / 32, 1), tb>>>(wv_ca, wt_vca, DMODEL, DMODEL);
    tp_kernel<<<dim3(DMODEL / 32, DMODEL / 32, 1), tb>>>(wo_ca, wt_oca, DMODEL, DMODEL);
    tp_kernel<<<dim3(DMODEL / 32, FDIM / 32, 1), tb>>>(w_ff1, wt_ff1, DMODEL, FDIM);
    tp_kernel<<<dim3(FDIM / 32, DMODEL / 32, 1), tb>>>(w_ff2, wt_ff2, FDIM, DMODEL);
    tp_kernel<<<dim3(DMODEL / 32, HD / 32, NH), tb>>>(wh1, wt_h1, DMODEL, HD);
    tp_kernel<<<dim3(HD / 32, OUTD / 32, NH), tb>>>(wh2, wt_h2, HD, OUTD);

    dim3 blk(THREADS);
    const int MG = BATCH / BM;  // 64

    // 1) h = x @ w_in + b_in + pos   (h doubles as "mem")
    gemm_tc<F_B2><<<dim3(DMODEL / BN, MG, 1), blk, SMB>>>(
        x, DIN, 0, wt_in, 0, h, DMODEL, 0, DIN, b_in, 0, pos, nullptr);

    // 2) t = ln1(h)
    ln_kernel<<<BATCH, 128>>>(h, t, ln1_g, ln1_b, DMODEL, 0);

    // 3) u = t @ wv_sa + bv_sa
    gemm_tc<0><<<dim3(DMODEL / BN, MG, 1), blk, SMB>>>(
        t, DMODEL, 0, wt_vsa, 0, u, DMODEL, 0, DMODEL, bv_sa, 0, nullptr, nullptr);

    // 4) hb = h + u @ wo_sa + bo_sa
    gemm_tc<F_RES><<<dim3(DMODEL / BN, MG, 1), blk, SMB>>>(
        u, DMODEL, 0, wt_osa, 0, hb, DMODEL, 0, DMODEL, bo_sa, 0, nullptr, h);

    // 5) t = h @ wv_ca + bv_ca   (h is still the pre-attn "mem")
    gemm_tc<0><<<dim3(DMODEL / BN, MG, 1), blk, SMB>>>(
        h, DMODEL, 0, wt_vca, 0, t, DMODEL, 0, DMODEL, bv_ca, 0, nullptr, nullptr);

    // 6) h = hb + t @ wo_ca + bo_ca
    gemm_tc<F_RES><<<dim3(DMODEL / BN, MG, 1), blk, SMB>>>(
        t, DMODEL, 0, wt_oca, 0, h, DMODEL, 0, DMODEL, bo_ca, 0, nullptr, hb);

    // 7) u = ln3(h)
    ln_kernel<<<BATCH, 128>>>(h, u, ln3_g, ln3_b, DMODEL, 0);

    // 8) ff = gelu(u @ w_ff1 + b_ff1)
    gemm_tc<F_GELU><<<dim3(FDIM / BN, MG, 1), blk, SMB>>>(
        u, DMODEL, 0, wt_ff1, 0, ff, FDIM, 0, DMODEL, b_ff1, 0, nullptr, nullptr);

    // 9) hb = h + ff @ w_ff2 + b_ff2
    gemm_tc<F_RES><<<dim3(DMODEL / BN, MG, 1), blk, SMB>>>(
        ff, FDIM, 0, wt_ff2, 0, hb, DMODEL, 0, FDIM, b_ff2, 0, nullptr, h);

    // 10) t = lnout(hb)
    ln_kernel<<<BATCH, 128>>>(hb, t, lnout_g, lnout_b, DMODEL, 0);

    // 11) zz = gelu(t @ wh1 + bh1), batched over heads
    gemm_tc<F_GELU><<<dim3(HD / BN, MG, NH), blk, SMB>>>(
        t, DMODEL, 0, wt_h1, (long)HD * DMODEL, zz, NH * HD, HD,
        DMODEL, bh1, HD, nullptr, nullptr);

    // 12) zz = ln_head(zz), per-head params, in place
    ln_kernel<<<BATCH * NH, 128>>>(zz, zz, lnh_g, lnh_b, HD, NH);

    // 13) out = zz @ wh2 + bh2, batched over heads
    gemm_tc<0><<<dim3(OUTD / BN, MG, NH), blk, SMB>>>(
        zz, NH * HD, HD, wt_h2, (long)OUTD * HD, out, NH * OUTD, OUTD,
        HD, bh2, OUTD, nullptr, nullptr);
}

// round 4
// speedup vs baseline: 1.7404x; 1.7404x over previous
#include <cuda_runtime.h>
#include <math.h>
#include <stdint.h>

// ---------------------------------------------------------------------------
// Shapes
// ---------------------------------------------------------------------------
#define BATCH  8192
#define DIN    4096
#define DMODEL 512
#define FDIM   2048
#define NH     3
#define HD     256
#define OUTD   896

// GEMM tile config (Round-1 proven skeleton)
#define BM 128
#define BN 128
#define BK 32
#define THREADS 256
#define AST 36                         // A smem row stride (conflict-free)
#define A_STAGE (BM * AST)             // 4608 floats
#define B_STAGE (BK * BN)              // 4096 floats (packed [4][128][8])
#define STAGE (A_STAGE + B_STAGE)      // 8704 floats
#define SMB (2 * STAGE * 4)            // 69632 B

// Epilogue flags
#define F_B2   1
#define F_GELU 2
#define F_RES  4

// ---------------------------------------------------------------------------
// Scratch
// ---------------------------------------------------------------------------
__device__ float g_h  [BATCH * DMODEL];
__device__ float g_hb [BATCH * DMODEL];
__device__ float g_t  [BATCH * DMODEL];
__device__ float g_u  [BATCH * DMODEL];
__device__ float g_ff [BATCH * FDIM];
__device__ float g_z  [BATCH * NH * HD];

// tf32-rounded, pair-packed weights: layout [K/8][N][8], pair (k,k+4) adjacent
__device__ float g_wp_in [DIN * DMODEL];
__device__ float g_wp_vsa[DMODEL * DMODEL];
__device__ float g_wp_osa[DMODEL * DMODEL];
__device__ float g_wp_vca[DMODEL * DMODEL];
__device__ float g_wp_oca[DMODEL * DMODEL];
__device__ float g_wp_ff1[DMODEL * FDIM];
__device__ float g_wp_ff2[FDIM * DMODEL];
__device__ float g_wp_h1 [NH * DMODEL * HD];
__device__ float g_wp_h2 [NH * HD * OUTD];

// ---------------------------------------------------------------------------
// Helpers
// ---------------------------------------------------------------------------
static __device__ __forceinline__ void cp16(float* sm, const float* gm) {
    unsigned s = (unsigned)__cvta_generic_to_shared(sm);
    asm volatile("cp.async.ca.shared.global [%0], [%1], 16;\n" :: "r"(s), "l"(gm));
}
static __device__ __forceinline__ unsigned f2tf32(float f) {
    unsigned u;
    asm("cvt.rna.tf32.f32 %0, %1;" : "=r"(u) : "f"(f));
    return u;
}
static __device__ __forceinline__ float gelu_exact(float v) {
    return 0.5f * v * (1.0f + erff(v * 0.70710678118654752f));
}

// ---------------------------------------------------------------------------
// tf32 GEMM, mma.sync m16n8k8, 256 thr, 32x64 warp tiles, zero-CVT inner loop.
// A row-major [M,K] fp32 (rounded at staging). B pre-packed [K/8][N][8] tf32.
// grid (N/BN, M/BM, z).
// ---------------------------------------------------------------------------
template<int FLAGS>
__global__ void __launch_bounds__(THREADS, 2) gemm_tc(
    const float* __restrict__ A, int lda, long sA,
    const float* __restrict__ B, int ldbN, long sB,
    float* __restrict__ C, int ldc, long sC,
    int K,
    const float* __restrict__ bias, int sBias,
    const float* __restrict__ bias2,
    const float* __restrict__ res)
{
    extern __shared__ float sm[];
    const int tid  = threadIdx.x;
    const int lane = tid & 31;
    const int warp = tid >> 5;
    const int wm = warp & 3;     // 4 warps along M: 32 rows each
    const int wn = warp >> 2;    // 2 warps along N: 64 cols each
    const int q  = lane >> 2, cc = lane & 3;

    const int z = blockIdx.z;
    A    += (long)z * sA;
    B    += (long)z * sB;
    C    += (long)z * sC;
    bias += (long)z * sBias;
    const float* resb = (FLAGS & F_RES) ? (res + (long)z * sC) : nullptr;

    const long mBase = (long)blockIdx.y * BM;
    const int  nBase = blockIdx.x * BN;
    const float* Ag = A + mBase * lda;

    const int numK = K / BK;

    // staging indices (Round-1 mapping)
    const int sr = tid >> 3;             // unused placeholder (kept simple below)
    (void)sr;

    float4 fA[4];
    auto ldgA = [&](int kt) {
#pragma unroll
        for (int i = 0; i < 4; i++) {
            int f = i * THREADS + tid;
            int r = f >> 3, c = (f & 7) * 4;
            fA[i] = *(const float4*)(Ag + (long)r * lda + kt * BK + c);
        }
    };
    auto stsA = [&](int buf) {
        float* As = sm + buf * STAGE;
#pragma unroll
        for (int i = 0; i < 4; i++) {
            int f = i * THREADS + tid;
            int r = f >> 3, c = (f & 7) * 4;
            float4 v = fA[i];
            *(uint4*)(As + r * AST + c) =
                make_uint4(f2tf32(v.x), f2tf32(v.y), f2tf32(v.z), f2tf32(v.w));
        }
    };
    auto cpB = [&](int kt, int buf) {
        float* Bs = sm + buf * STAGE + A_STAGE;
#pragma unroll
        for (int i = 0; i < 4; i++) {
            int idx = i * THREADS + tid;           // 0..1023
            int half = idx & 1;
            int n = (idx >> 1) & 127;
            int g = idx >> 8;                       // 0..3
            const float* src = B + ((long)(kt * 4 + g) * ldbN + nBase + n) * 8 + half * 4;
            cp16(Bs + (g * 128 + n) * 8 + half * 4, src);
        }
    };

    float acc[2][8][4];
#pragma unroll
    for (int a = 0; a < 2; a++)
#pragma unroll
        for (int b = 0; b < 8; b++)
#pragma unroll
            for (int c = 0; c < 4; c++) acc[a][b][c] = 0.f;

    // ---- prologue ----
    ldgA(0); stsA(0); cpB(0, 0);
    asm volatile("cp.async.commit_group;\n" ::: "memory");

    for (int kt = 0; kt < numK; kt++) {
        asm volatile("cp.async.wait_group 0;\n" ::: "memory");
        __syncthreads();

        if (kt + 1 < numK) {
            ldgA(kt + 1);
            cpB(kt + 1, (kt + 1) & 1);
            asm volatile("cp.async.commit_group;\n" ::: "memory");
        }

        const float* As = sm + (kt & 1) * STAGE + (wm * 32) * AST;
        const float* Bs = sm + (kt & 1) * STAGE + A_STAGE;

#pragma unroll
        for (int ks = 0; ks < 4; ks++) {
            uint32_t af[2][4];
#pragma unroll
            for (int mi = 0; mi < 2; mi++) {
                const float* ap = As + (mi * 16 + q) * AST + ks * 8 + cc;
                af[mi][0] = __float_as_uint(ap[0]);
                af[mi][1] = __float_as_uint(ap[8 * AST]);
                af[mi][2] = __float_as_uint(ap[4]);
                af[mi][3] = __float_as_uint(ap[8 * AST + 4]);
            }
            uint32_t bf[8][2];
#pragma unroll
            for (int ni = 0; ni < 8; ni++) {
                uint2 bv = *(const uint2*)(Bs + ((ks * 128 + wn * 64 + ni * 8 + q) * 8 + cc * 2));
                bf[ni][0] = bv.x; bf[ni][1] = bv.y;
            }
#pragma unroll
            for (int mi = 0; mi < 2; mi++)
#pragma unroll
                for (int ni = 0; ni < 8; ni++)
                    asm volatile(
                        "mma.sync.aligned.m16n8k8.row.col.f32.tf32.tf32.f32 "
                        "{%0,%1,%2,%3},{%4,%5,%6,%7},{%8,%9},{%0,%1,%2,%3};\n"
                        : "+f"(acc[mi][ni][0]), "+f"(acc[mi][ni][1]),
                          "+f"(acc[mi][ni][2]), "+f"(acc[mi][ni][3])
                        : "r"(af[mi][0]), "r"(af[mi][1]), "r"(af[mi][2]), "r"(af[mi][3]),
                          "r"(bf[ni][0]), "r"(bf[ni][1]));
        }

        if (kt + 1 < numK) stsA((kt + 1) & 1);   // A data arrived during compute
    }

    // ---- fused epilogue ----
    const int rBase = (int)mBase + wm * 32;
    const int cBase = nBase + wn * 64;
#pragma unroll
    for (int mi = 0; mi < 2; mi++) {
#pragma unroll
        for (int ni = 0; ni < 8; ni++) {
            int c = cBase + ni * 8 + cc * 2;
            float b0 = bias[c], b1 = bias[c + 1];
            if (FLAGS & F_B2) { b0 += bias2[c]; b1 += bias2[c + 1]; }
#pragma unroll
            for (int h = 0; h < 2; h++) {
                long row = rBase + mi * 16 + q + 8 * h;
                float v0 = acc[mi][ni][2 * h + 0] + b0;
                float v1 = acc[mi][ni][2 * h + 1] + b1;
                if (FLAGS & F_GELU) { v0 = gelu_exact(v0); v1 = gelu_exact(v1); }
                long idx = row * ldc + c;
                if (FLAGS & F_RES) {
                    float2 rr = *(const float2*)(resb + idx);
                    v0 += rr.x; v1 += rr.y;
                }
                *(float2*)(C + idx) = make_float2(v0, v1);
            }
        }
    }
}

// ---------------------------------------------------------------------------
// Weight pack: in [K,N] fp32 -> out [K/8][N][8] tf32, pair order
// {k0,k4,k1,k5,k2,k6,k3,k7} within each 8-k group. grid (N/128, K/8, Z).
// ---------------------------------------------------------------------------
__global__ void pack_kernel(const float* __restrict__ in, float* __restrict__ out,
                            int K, int N)
{
    const long zo = (long)blockIdx.z * K * N;
    const int n = blockIdx.x * 128 + threadIdx.x;
    const int g = blockIdx.y;
    float v[8];
#pragma unroll
    for (int k = 0; k < 8; k++)
        v[k] = in[zo + (long)(g * 8 + k) * N + n];
    float* o = out + zo + ((long)g * N + n) * 8;
    *(uint4*)(o)     = make_uint4(f2tf32(v[0]), f2tf32(v[4]), f2tf32(v[1]), f2tf32(v[5]));
    *(uint4*)(o + 4) = make_uint4(f2tf32(v[2]), f2tf32(v[6]), f2tf32(v[3]), f2tf32(v[7]));
}

// ---------------------------------------------------------------------------
// Row LayerNorm
// ---------------------------------------------------------------------------
__global__ void ln_kernel(const float* __restrict__ in, float* __restrict__ out,
                          const float* __restrict__ g, const float* __restrict__ b,
                          int C, int headMod)
{
    __shared__ float red[8];
    const int row = blockIdx.x;
    const float* x = in + (long)row * C;
    float* y = out + (long)row * C;
    const int go = headMod ? (row % headMod) * C : 0;

    float s = 0.f, s2 = 0.f;
    for (int i = threadIdx.x; i < C; i += 128) {
        float v = x[i]; s += v; s2 += v * v;
    }
#pragma unroll
    for (int o = 16; o; o >>= 1) {
        s  += __shfl_xor_sync(0xffffffffu, s, o);
        s2 += __shfl_xor_sync(0xffffffffu, s2, o);
    }
    const int w = threadIdx.x >> 5;
    if ((threadIdx.x & 31) == 0) { red[w] = s; red[4 + w] = s2; }
    __syncthreads();
    if (threadIdx.x == 0) {
        float ts = 0.f, ts2 = 0.f;
#pragma unroll
        for (int i = 0; i < 4; i++) { ts += red[i]; ts2 += red[4 + i]; }
        red[0] = ts; red[4] = ts2;
    }
    __syncthreads();
    const float mean = red[0] / C;
    const float var  = red[4] / C - mean * mean;
    const float inv  = rsqrtf(var + 1e-5f);
    for (int i = threadIdx.x; i < C; i += 128)
        y[i] = (x[i] - mean) * inv * g[go + i] + b[go + i];
}

// ---------------------------------------------------------------------------
// Launch
// ---------------------------------------------------------------------------
extern "C" void kernel_launch(void* const* d_in, const int* in_sizes, int n_in,
                              void* d_out, int out_size)
{
    const float* x      = (const float*)d_in[0];
    const float* w_in   = (const float*)d_in[1];
    const float* b_in   = (const float*)d_in[2];
    const float* pos    = (const float*)d_in[3];
    const float* ln1_g  = (const float*)d_in[4];
    const float* ln1_b  = (const float*)d_in[5];
    const float* wv_sa  = (const float*)d_in[6];
    const float* bv_sa  = (const float*)d_in[7];
    const float* wo_sa  = (const float*)d_in[8];
    const float* bo_sa  = (const float*)d_in[9];
    const float* wv_ca  = (const float*)d_in[12];
    const float* bv_ca  = (const float*)d_in[13];
    const float* wo_ca  = (const float*)d_in[14];
    const float* bo_ca  = (const float*)d_in[15];
    const float* ln3_g  = (const float*)d_in[16];
    const float* ln3_b  = (const float*)d_in[17];
    const float* w_ff1  = (const float*)d_in[18];
    const float* b_ff1  = (const float*)d_in[19];
    const float* w_ff2  = (const float*)d_in[20];
    const float* b_ff2  = (const float*)d_in[21];
    const float* lnout_g= (const float*)d_in[22];
    const float* lnout_b= (const float*)d_in[23];
    const float* wh1    = (const float*)d_in[24];
    const float* bh1    = (const float*)d_in[25];
    const float* lnh_g  = (const float*)d_in[26];
    const float* lnh_b  = (const float*)d_in[27];
    const float* wh2    = (const float*)d_in[28];
    const float* bh2    = (const float*)d_in[29];
    float* out = (float*)d_out;

    float *h, *hb, *t, *u, *ff, *zz;
    float *wp_in, *wp_vsa, *wp_osa, *wp_vca, *wp_oca, *wp_ff1, *wp_ff2, *wp_h1, *wp_h2;
    cudaGetSymbolAddress((void**)&h,  g_h);
    cudaGetSymbolAddress((void**)&hb, g_hb);
    cudaGetSymbolAddress((void**)&t,  g_t);
    cudaGetSymbolAddress((void**)&u,  g_u);
    cudaGetSymbolAddress((void**)&ff, g_ff);
    cudaGetSymbolAddress((void**)&zz, g_z);
    cudaGetSymbolAddress((void**)&wp_in,  g_wp_in);
    cudaGetSymbolAddress((void**)&wp_vsa, g_wp_vsa);
    cudaGetSymbolAddress((void**)&wp_osa, g_wp_osa);
    cudaGetSymbolAddress((void**)&wp_vca, g_wp_vca);
    cudaGetSymbolAddress((void**)&wp_oca, g_wp_oca);
    cudaGetSymbolAddress((void**)&wp_ff1, g_wp_ff1);
    cudaGetSymbolAddress((void**)&wp_ff2, g_wp_ff2);
    cudaGetSymbolAddress((void**)&wp_h1,  g_wp_h1);
    cudaGetSymbolAddress((void**)&wp_h2,  g_wp_h2);

    cudaFuncSetAttribute(gemm_tc<F_B2>,   cudaFuncAttributeMaxDynamicSharedMemorySize, SMB);
    cudaFuncSetAttribute(gemm_tc<0>,      cudaFuncAttributeMaxDynamicSharedMemorySize, SMB);
    cudaFuncSetAttribute(gemm_tc<F_RES>,  cudaFuncAttributeMaxDynamicSharedMemorySize, SMB);
    cudaFuncSetAttribute(gemm_tc<F_GELU>, cudaFuncAttributeMaxDynamicSharedMemorySize, SMB);

    // weight packing: [K,N] -> [K/8][N][8] tf32, pair-ordered
    pack_kernel<<<dim3(DMODEL / 128, DIN / 8, 1), 128>>>(w_in,  wp_in,  DIN, DMODEL);
    pack_kernel<<<dim3(DMODEL / 128, DMODEL / 8, 1), 128>>>(wv_sa, wp_vsa, DMODEL, DMODEL);
    pack_kernel<<<dim3(DMODEL / 128, DMODEL / 8, 1), 128>>>(wo_sa, wp_osa, DMODEL, DMODEL);
    pack_kernel<<<dim3(DMODEL / 128, DMODEL / 8, 1), 128>>>(wv_ca, wp_vca, DMODEL, DMODEL);
    pack_kernel<<<dim3(DMODEL / 128, DMODEL / 8, 1), 128>>>(wo_ca, wp_oca, DMODEL, DMODEL);
    pack_kernel<<<dim3(FDIM / 128, DMODEL / 8, 1), 128>>>(w_ff1, wp_ff1, DMODEL, FDIM);
    pack_kernel<<<dim3(DMODEL / 128, FDIM / 8, 1), 128>>>(w_ff2, wp_ff2, FDIM, DMODEL);
    pack_kernel<<<dim3(HD / 128, DMODEL / 8, NH), 128>>>(wh1, wp_h1, DMODEL, HD);
    pack_kernel<<<dim3(OUTD / 128, HD / 8, NH), 128>>>(wh2, wp_h2, HD, OUTD);

    dim3 blk(THREADS);
    const int MG = BATCH / BM;  // 64

    // 1) h = x @ w_in + b_in + pos   (h doubles as "mem")
    gemm_tc<F_B2><<<dim3(DMODEL / BN, MG, 1), blk, SMB>>>(
        x, DIN, 0, wp_in, DMODEL, 0, h, DMODEL, 0, DIN, b_in, 0, pos, nullptr);

    // 2) t = ln1(h)
    ln_kernel<<<BATCH, 128>>>(h, t, ln1_g, ln1_b, DMODEL, 0);

    // 3) u = t @ wv_sa + bv_sa
    gemm_tc<0><<<dim3(DMODEL / BN, MG, 1), blk, SMB>>>(
        t, DMODEL, 0, wp_vsa, DMODEL, 0, u, DMODEL, 0, DMODEL, bv_sa, 0, nullptr, nullptr);

    // 4) hb = h + u @ wo_sa + bo_sa
    gemm_tc<F_RES><<<dim3(DMODEL / BN, MG, 1), blk, SMB>>>(
        u, DMODEL, 0, wp_osa, DMODEL, 0, hb, DMODEL, 0, DMODEL, bo_sa, 0, nullptr, h);

    // 5) t = h @ wv_ca + bv_ca   (h = pre-attn "mem")
    gemm_tc<0><<<dim3(DMODEL / BN, MG, 1), blk, SMB>>>(
        h, DMODEL, 0, wp_vca, DMODEL, 0, t, DMODEL, 0, DMODEL, bv_ca, 0, nullptr, nullptr);

    // 6) h = hb + t @ wo_ca + bo_ca
    gemm_tc<F_RES><<<dim3(DMODEL / BN, MG, 1), blk, SMB>>>(
        t, DMODEL, 0, wp_oca, DMODEL, 0, h, DMODEL, 0, DMODEL, bo_ca, 0, nullptr, hb);

    // 7) u = ln3(h)
    ln_kernel<<<BATCH, 128>>>(h, u, ln3_g, ln3_b, DMODEL, 0);

    // 8) ff = gelu(u @ w_ff1 + b_ff1)
    gemm_tc<F_GELU><<<dim3(FDIM / BN, MG, 1), blk, SMB>>>(
        u, DMODEL, 0, wp_ff1, FDIM, 0, ff, FDIM, 0, DMODEL, b_ff1, 0, nullptr, nullptr);

    // 9) hb = h + ff @ w_ff2 + b_ff2
    gemm_tc<F_RES><<<dim3(DMODEL / BN, MG, 1), blk, SMB>>>(
        ff, FDIM, 0, wp_ff2, DMODEL, 0, hb, DMODEL, 0, FDIM, b_ff2, 0, nullptr, h);

    // 10) t = lnout(hb)
    ln_kernel<<<BATCH, 128>>>(hb, t, lnout_g, lnout_b, DMODEL, 0);

    // 11) zz = gelu(t @ wh1 + bh1), batched over heads
    gemm_tc<F_GELU><<<dim3(HD / BN, MG, NH), blk, SMB>>>(
        t, DMODEL, 0, wp_h1, HD, (long)DMODEL * HD, zz, NH * HD, HD,
        DMODEL, bh1, HD, nullptr, nullptr);

    // 12) zz = ln_head(zz), per-head params, in place
    ln_kernel<<<BATCH * NH, 128>>>(zz, zz, lnh_g, lnh_b, HD, NH);

    // 13) out = zz @ wh2 + bh2, batched over heads
    gemm_tc<0><<<dim3(OUTD / BN, MG, NH), blk, SMB>>>(
        zz, NH * HD, HD, wp_h2, OUTD, (long)HD * OUTD, out, NH * OUTD, OUTD,
        HD, bh2, OUTD, nullptr, nullptr);
}

// round 5
// speedup vs baseline: 1.7512x; 1.0062x over previous
#include <cuda_runtime.h>
#include <math.h>
#include <stdint.h>

// ---------------------------------------------------------------------------
// Shapes
// ---------------------------------------------------------------------------
#define BATCH  8192
#define DIN    4096
#define DMODEL 512
#define FDIM   2048
#define NH     3
#define HD     256
#define OUTD   896

// big GEMM tile (128x256, 8 warps of 64x64)
#define BM 128
#define BN 256
#define BK 32
#define THREADS 256
#define AST 36
#define A_STAGE (BM * AST)                 // 4608 floats
#define B_STAGE (4 * BN * 8)               // 8192 floats  [g][n][8]
#define STAGE (A_STAGE + B_STAGE)          // 12800 floats
#define SMB_BIG (2 * STAGE * 4)            // 102400 B

// small GEMM tile (128x128, 8 warps of 32x64) - for N=896 head gemm
#define SBN 128
#define SB_STAGE (4 * SBN * 8)             // 4096 floats
#define SSTAGE (A_STAGE + SB_STAGE)        // 8704 floats
#define SMB_SM (2 * SSTAGE * 4)            // 69632 B

// Epilogue flags
#define F_B2   1
#define F_GELU 2
#define F_RES  4

// ---------------------------------------------------------------------------
// Scratch
// ---------------------------------------------------------------------------
__device__ float g_h  [BATCH * DMODEL];
__device__ float g_hb [BATCH * DMODEL];
__device__ float g_t  [BATCH * DMODEL];
__device__ float g_u  [BATCH * DMODEL];
__device__ float g_ff [BATCH * FDIM];
__device__ float g_z  [BATCH * NH * HD];

// tf32-rounded, pair-packed weights: [K/8][N][8], pairs (k,k+4) adjacent
__device__ float g_wp_in [DIN * DMODEL];
__device__ float g_wp_vsa[DMODEL * DMODEL];
__device__ float g_wp_osa[DMODEL * DMODEL];
__device__ float g_wp_vca[DMODEL * DMODEL];
__device__ float g_wp_oca[DMODEL * DMODEL];
__device__ float g_wp_ff1[DMODEL * FDIM];
__device__ float g_wp_ff2[FDIM * DMODEL];
__device__ float g_wp_h1 [NH * DMODEL * HD];
__device__ float g_wp_h2 [NH * HD * OUTD];

// ---------------------------------------------------------------------------
// Helpers
// ---------------------------------------------------------------------------
static __device__ __forceinline__ void cp16(float* sm, const float* gm) {
    unsigned s = (unsigned)__cvta_generic_to_shared(sm);
    asm volatile("cp.async.ca.shared.global [%0], [%1], 16;\n" :: "r"(s), "l"(gm));
}
static __device__ __forceinline__ unsigned f2tf32(float f) {
    unsigned u;
    asm("cvt.rna.tf32.f32 %0, %1;" : "=r"(u) : "f"(f));
    return u;
}
static __device__ __forceinline__ float gelu_exact(float v) {
    return 0.5f * v * (1.0f + erff(v * 0.70710678118654752f));
}
#define MMA_TF32(acc, a0, a1, a2, a3, b0, b1)                                  \
    asm volatile(                                                              \
        "mma.sync.aligned.m16n8k8.row.col.f32.tf32.tf32.f32 "                  \
        "{%0,%1,%2,%3},{%4,%5,%6,%7},{%8,%9},{%0,%1,%2,%3};\n"                 \
        : "+f"((acc)[0]), "+f"((acc)[1]), "+f"((acc)[2]), "+f"((acc)[3])       \
        : "r"(a0), "r"(a1), "r"(a2), "r"(a3), "r"(b0), "r"(b1))

// ---------------------------------------------------------------------------
// BIG: 128x256 CTA tile, 8 warps (2 M x 4 N) of 64x64.
// A row-major [M,K] fp32 (rna->tf32 at staging). B packed [K/8][N][8] tf32.
// grid (N/256, M/128, z). 256 threads, 1 CTA/SM.
// ---------------------------------------------------------------------------
template<int FLAGS>
__global__ void __launch_bounds__(THREADS, 1) gemm_big(
    const float* __restrict__ A, int lda, long sA,
    const float* __restrict__ B, int ldbN, long sB,
    float* __restrict__ C, int ldc, long sC,
    int K,
    const float* __restrict__ bias, int sBias,
    const float* __restrict__ bias2,
    const float* __restrict__ res)
{
    extern __shared__ float sm[];
    const int tid  = threadIdx.x;
    const int lane = tid & 31;
    const int warp = tid >> 5;
    const int wm = warp & 1;     // 2 warps along M: 64 rows each
    const int wn = warp >> 1;    // 4 warps along N: 64 cols each
    const int q  = lane >> 2, cc = lane & 3;

    const int z = blockIdx.z;
    A    += (long)z * sA;
    B    += (long)z * sB;
    C    += (long)z * sC;
    bias += (long)z * sBias;
    const float* resb = (FLAGS & F_RES) ? (res + (long)z * sC) : nullptr;

    const long mBase = (long)blockIdx.y * BM;
    const int  nBase = blockIdx.x * BN;
    const float* Ag = A + mBase * lda;

    const int numK = K / BK;

    float4 fA[4];
    auto ldgA = [&](int kt) {
#pragma unroll
        for (int i = 0; i < 4; i++) {
            int f = i * THREADS + tid;
            int r = f >> 3, c = (f & 7) * 4;
            fA[i] = *(const float4*)(Ag + (long)r * lda + kt * BK + c);
        }
    };
    auto stsA = [&](int buf) {
        float* As = sm + buf * STAGE;
#pragma unroll
        for (int i = 0; i < 4; i++) {
            int f = i * THREADS + tid;
            int r = f >> 3, c = (f & 7) * 4;
            float4 v = fA[i];
            *(uint4*)(As + r * AST + c) =
                make_uint4(f2tf32(v.x), f2tf32(v.y), f2tf32(v.z), f2tf32(v.w));
        }
    };
    auto cpB = [&](int kt, int buf) {
        float* Bs = sm + buf * STAGE + A_STAGE;
#pragma unroll
        for (int i = 0; i < 8; i++) {
            int idx = i * THREADS + tid;            // 0..2047
            int half = idx & 1;
            int n = (idx >> 1) & 255;
            int g = idx >> 9;                        // 0..3
            const float* src = B + ((long)(kt * 4 + g) * ldbN + nBase + n) * 8 + half * 4;
            cp16(Bs + (g * BN + n) * 8 + half * 4, src);
        }
    };

    float acc[4][8][4];
#pragma unroll
    for (int a = 0; a < 4; a++)
#pragma unroll
        for (int b = 0; b < 8; b++)
#pragma unroll
            for (int c = 0; c < 4; c++) acc[a][b][c] = 0.f;

    // ---- prologue ----
    ldgA(0); stsA(0); cpB(0, 0);
    asm volatile("cp.async.commit_group;\n" ::: "memory");

    for (int kt = 0; kt < numK; kt++) {
        asm volatile("cp.async.wait_group 0;\n" ::: "memory");
        __syncthreads();

        if (kt + 1 < numK) {
            ldgA(kt + 1);
            cpB(kt + 1, (kt + 1) & 1);
            asm volatile("cp.async.commit_group;\n" ::: "memory");
        }

        const float* As = sm + (kt & 1) * STAGE + (wm * 64) * AST;
        const float* Bs = sm + (kt & 1) * STAGE + A_STAGE;

#pragma unroll
        for (int ks = 0; ks < 4; ks++) {
            uint32_t af[4][4];
#pragma unroll
            for (int mi = 0; mi < 4; mi++) {
                const float* ap = As + (mi * 16 + q) * AST + ks * 8 + cc;
                af[mi][0] = __float_as_uint(ap[0]);
                af[mi][1] = __float_as_uint(ap[8 * AST]);
                af[mi][2] = __float_as_uint(ap[4]);
                af[mi][3] = __float_as_uint(ap[8 * AST + 4]);
            }
            uint32_t bf[8][2];
#pragma unroll
            for (int ni = 0; ni < 8; ni++) {
                uint2 bv = *(const uint2*)(Bs + ((ks * BN + wn * 64 + ni * 8 + q) * 8 + cc * 2));
                bf[ni][0] = bv.x; bf[ni][1] = bv.y;
            }
#pragma unroll
            for (int mi = 0; mi < 4; mi++)
#pragma unroll
                for (int ni = 0; ni < 8; ni++)
                    MMA_TF32(acc[mi][ni], af[mi][0], af[mi][1], af[mi][2], af[mi][3],
                             bf[ni][0], bf[ni][1]);
        }

        if (kt + 1 < numK) stsA((kt + 1) & 1);
    }

    // ---- fused epilogue ----
    const int rBase = (int)mBase + wm * 64;
    const int cBase = nBase + wn * 64;
#pragma unroll
    for (int mi = 0; mi < 4; mi++) {
#pragma unroll
        for (int ni = 0; ni < 8; ni++) {
            int c = cBase + ni * 8 + cc * 2;
            float b0 = bias[c], b1 = bias[c + 1];
            if (FLAGS & F_B2) { b0 += bias2[c]; b1 += bias2[c + 1]; }
#pragma unroll
            for (int h = 0; h < 2; h++) {
                long row = rBase + mi * 16 + q + 8 * h;
                float v0 = acc[mi][ni][2 * h + 0] + b0;
                float v1 = acc[mi][ni][2 * h + 1] + b1;
                if (FLAGS & F_GELU) { v0 = gelu_exact(v0); v1 = gelu_exact(v1); }
                long idx = row * ldc + c;
                if (FLAGS & F_RES) {
                    float2 rr = *(const float2*)(resb + idx);
                    v0 += rr.x; v1 += rr.y;
                }
                *(float2*)(C + idx) = make_float2(v0, v1);
            }
        }
    }
}

// ---------------------------------------------------------------------------
// SMALL: 128x128 CTA tile, 8 warps (4 M x 2 N) of 32x64 (R4 proven kernel).
// Used for the N=896 head GEMM.
// ---------------------------------------------------------------------------
template<int FLAGS>
__global__ void __launch_bounds__(THREADS, 2) gemm_sm(
    const float* __restrict__ A, int lda, long sA,
    const float* __restrict__ B, int ldbN, long sB,
    float* __restrict__ C, int ldc, long sC,
    int K,
    const float* __restrict__ bias, int sBias)
{
    extern __shared__ float sm[];
    const int tid  = threadIdx.x;
    const int lane = tid & 31;
    const int warp = tid >> 5;
    const int wm = warp & 3;
    const int wn = warp >> 2;
    const int q  = lane >> 2, cc = lane & 3;

    const int z = blockIdx.z;
    A    += (long)z * sA;
    B    += (long)z * sB;
    C    += (long)z * sC;
    bias += (long)z * sBias;

    const long mBase = (long)blockIdx.y * BM;
    const int  nBase = blockIdx.x * SBN;
    const float* Ag = A + mBase * lda;

    const int numK = K / BK;

    float4 fA[4];
    auto ldgA = [&](int kt) {
#pragma unroll
        for (int i = 0; i < 4; i++) {
            int f = i * THREADS + tid;
            int r = f >> 3, c = (f & 7) * 4;
            fA[i] = *(const float4*)(Ag + (long)r * lda + kt * BK + c);
        }
    };
    auto stsA = [&](int buf) {
        float* As = sm + buf * SSTAGE;
#pragma unroll
        for (int i = 0; i < 4; i++) {
            int f = i * THREADS + tid;
            int r = f >> 3, c = (f & 7) * 4;
            float4 v = fA[i];
            *(uint4*)(As + r * AST + c) =
                make_uint4(f2tf32(v.x), f2tf32(v.y), f2tf32(v.z), f2tf32(v.w));
        }
    };
    auto cpB = [&](int kt, int buf) {
        float* Bs = sm + buf * SSTAGE + A_STAGE;
#pragma unroll
        for (int i = 0; i < 4; i++) {
            int idx = i * THREADS + tid;           // 0..1023
            int half = idx & 1;
            int n = (idx >> 1) & 127;
            int g = idx >> 8;
            const float* src = B + ((long)(kt * 4 + g) * ldbN + nBase + n) * 8 + half * 4;
            cp16(Bs + (g * SBN + n) * 8 + half * 4, src);
        }
    };

    float acc[2][8][4];
#pragma unroll
    for (int a = 0; a < 2; a++)
#pragma unroll
        for (int b = 0; b < 8; b++)
#pragma unroll
            for (int c = 0; c < 4; c++) acc[a][b][c] = 0.f;

    ldgA(0); stsA(0); cpB(0, 0);
    asm volatile("cp.async.commit_group;\n" ::: "memory");

    for (int kt = 0; kt < numK; kt++) {
        asm volatile("cp.async.wait_group 0;\n" ::: "memory");
        __syncthreads();

        if (kt + 1 < numK) {
            ldgA(kt + 1);
            cpB(kt + 1, (kt + 1) & 1);
            asm volatile("cp.async.commit_group;\n" ::: "memory");
        }

        const float* As = sm + (kt & 1) * SSTAGE + (wm * 32) * AST;
        const float* Bs = sm + (kt & 1) * SSTAGE + A_STAGE;

#pragma unroll
        for (int ks = 0; ks < 4; ks++) {
            uint32_t af[2][4];
#pragma unroll
            for (int mi = 0; mi < 2; mi++) {
                const float* ap = As + (mi * 16 + q) * AST + ks * 8 + cc;
                af[mi][0] = __float_as_uint(ap[0]);
                af[mi][1] = __float_as_uint(ap[8 * AST]);
                af[mi][2] = __float_as_uint(ap[4]);
                af[mi][3] = __float_as_uint(ap[8 * AST + 4]);
            }
            uint32_t bf[8][2];
#pragma unroll
            for (int ni = 0; ni < 8; ni++) {
                uint2 bv = *(const uint2*)(Bs + ((ks * SBN + wn * 64 + ni * 8 + q) * 8 + cc * 2));
                bf[ni][0] = bv.x; bf[ni][1] = bv.y;
            }
#pragma unroll
            for (int mi = 0; mi < 2; mi++)
#pragma unroll
                for (int ni = 0; ni < 8; ni++)
                    MMA_TF32(acc[mi][ni], af[mi][0], af[mi][1], af[mi][2], af[mi][3],
                             bf[ni][0], bf[ni][1]);
        }

        if (kt + 1 < numK) stsA((kt + 1) & 1);
    }

    const int rBase = (int)mBase + wm * 32;
    const int cBase = nBase + wn * 64;
#pragma unroll
    for (int mi = 0; mi < 2; mi++) {
#pragma unroll
        for (int ni = 0; ni < 8; ni++) {
            int c = cBase + ni * 8 + cc * 2;
            float b0 = bias[c], b1 = bias[c + 1];
#pragma unroll
            for (int h = 0; h < 2; h++) {
                long row = rBase + mi * 16 + q + 8 * h;
                float v0 = acc[mi][ni][2 * h + 0] + b0;
                float v1 = acc[mi][ni][2 * h + 1] + b1;
                long idx = row * ldc + c;
                if (FLAGS & F_GELU) { v0 = gelu_exact(v0); v1 = gelu_exact(v1); }
                *(float2*)(C + idx) = make_float2(v0, v1);
            }
        }
    }
}

// ---------------------------------------------------------------------------
// Weight pack: [K,N] fp32 -> [K/8][N][8] tf32, pair order {k0,k4,k1,k5,k2,k6,k3,k7}
// ---------------------------------------------------------------------------
__global__ void pack_kernel(const float* __restrict__ in, float* __restrict__ out,
                            int K, int N)
{
    const long zo = (long)blockIdx.z * K * N;
    const int n = blockIdx.x * 128 + threadIdx.x;
    const int g = blockIdx.y;
    float v[8];
#pragma unroll
    for (int k = 0; k < 8; k++)
        v[k] = in[zo + (long)(g * 8 + k) * N + n];
    float* o = out + zo + ((long)g * N + n) * 8;
    *(uint4*)(o)     = make_uint4(f2tf32(v[0]), f2tf32(v[4]), f2tf32(v[1]), f2tf32(v[5]));
    *(uint4*)(o + 4) = make_uint4(f2tf32(v[2]), f2tf32(v[6]), f2tf32(v[3]), f2tf32(v[7]));
}

// ---------------------------------------------------------------------------
// Row LayerNorm
// ---------------------------------------------------------------------------
__global__ void ln_kernel(const float* __restrict__ in, float* __restrict__ out,
                          const float* __restrict__ g, const float* __restrict__ b,
                          int C, int headMod)
{
    __shared__ float red[8];
    const int row = blockIdx.x;
    const float* x = in + (long)row * C;
    float* y = out + (long)row * C;
    const int go = headMod ? (row % headMod) * C : 0;

    float s = 0.f, s2 = 0.f;
    for (int i = threadIdx.x; i < C; i += 128) {
        float v = x[i]; s += v; s2 += v * v;
    }
#pragma unroll
    for (int o = 16; o; o >>= 1) {
        s  += __shfl_xor_sync(0xffffffffu, s, o);
        s2 += __shfl_xor_sync(0xffffffffu, s2, o);
    }
    const int w = threadIdx.x >> 5;
    if ((threadIdx.x & 31) == 0) { red[w] = s; red[4 + w] = s2; }
    __syncthreads();
    if (threadIdx.x == 0) {
        float ts = 0.f, ts2 = 0.f;
#pragma unroll
        for (int i = 0; i < 4; i++) { ts += red[i]; ts2 += red[4 + i]; }
        red[0] = ts; red[4] = ts2;
    }
    __syncthreads();
    const float mean = red[0] / C;
    const float var  = red[4] / C - mean * mean;
    const float inv  = rsqrtf(var + 1e-5f);
    for (int i = threadIdx.x; i < C; i += 128)
        y[i] = (x[i] - mean) * inv * g[go + i] + b[go + i];
}

// ---------------------------------------------------------------------------
// Launch
// ---------------------------------------------------------------------------
extern "C" void kernel_launch(void* const* d_in, const int* in_sizes, int n_in,
                              void* d_out, int out_size)
{
    const float* x      = (const float*)d_in[0];
    const float* w_in   = (const float*)d_in[1];
    const float* b_in   = (const float*)d_in[2];
    const float* pos    = (const float*)d_in[3];
    const float* ln1_g  = (const float*)d_in[4];
    const float* ln1_b  = (const float*)d_in[5];
    const float* wv_sa  = (const float*)d_in[6];
    const float* bv_sa  = (const float*)d_in[7];
    const float* wo_sa  = (const float*)d_in[8];
    const float* bo_sa  = (const float*)d_in[9];
    const float* wv_ca  = (const float*)d_in[12];
    const float* bv_ca  = (const float*)d_in[13];
    const float* wo_ca  = (const float*)d_in[14];
    const float* bo_ca  = (const float*)d_in[15];
    const float* ln3_g  = (const float*)d_in[16];
    const float* ln3_b  = (const float*)d_in[17];
    const float* w_ff1  = (const float*)d_in[18];
    const float* b_ff1  = (const float*)d_in[19];
    const float* w_ff2  = (const float*)d_in[20];
    const float* b_ff2  = (const float*)d_in[21];
    const float* lnout_g= (const float*)d_in[22];
    const float* lnout_b= (const float*)d_in[23];
    const float* wh1    = (const float*)d_in[24];
    const float* bh1    = (const float*)d_in[25];
    const float* lnh_g  = (const float*)d_in[26];
    const float* lnh_b  = (const float*)d_in[27];
    const float* wh2    = (const float*)d_in[28];
    const float* bh2    = (const float*)d_in[29];
    float* out = (float*)d_out;

    float *h, *hb, *t, *u, *ff, *zz;
    float *wp_in, *wp_vsa, *wp_osa, *wp_vca, *wp_oca, *wp_ff1, *wp_ff2, *wp_h1, *wp_h2;
    cudaGetSymbolAddress((void**)&h,  g_h);
    cudaGetSymbolAddress((void**)&hb, g_hb);
    cudaGetSymbolAddress((void**)&t,  g_t);
    cudaGetSymbolAddress((void**)&u,  g_u);
    cudaGetSymbolAddress((void**)&ff, g_ff);
    cudaGetSymbolAddress((void**)&zz, g_z);
    cudaGetSymbolAddress((void**)&wp_in,  g_wp_in);
    cudaGetSymbolAddress((void**)&wp_vsa, g_wp_vsa);
    cudaGetSymbolAddress((void**)&wp_osa, g_wp_osa);
    cudaGetSymbolAddress((void**)&wp_vca, g_wp_vca);
    cudaGetSymbolAddress((void**)&wp_oca, g_wp_oca);
    cudaGetSymbolAddress((void**)&wp_ff1, g_wp_ff1);
    cudaGetSymbolAddress((void**)&wp_ff2, g_wp_ff2);
    cudaGetSymbolAddress((void**)&wp_h1,  g_wp_h1);
    cudaGetSymbolAddress((void**)&wp_h2,  g_wp_h2);

    cudaFuncSetAttribute(gemm_big<F_B2>,   cudaFuncAttributeMaxDynamicSharedMemorySize, SMB_BIG);
    cudaFuncSetAttribute(gemm_big<0>,      cudaFuncAttributeMaxDynamicSharedMemorySize, SMB_BIG);
    cudaFuncSetAttribute(gemm_big<F_RES>,  cudaFuncAttributeMaxDynamicSharedMemorySize, SMB_BIG);
    cudaFuncSetAttribute(gemm_big<F_GELU>, cudaFuncAttributeMaxDynamicSharedMemorySize, SMB_BIG);
    cudaFuncSetAttribute(gemm_sm<0>,       cudaFuncAttributeMaxDynamicSharedMemorySize, SMB_SM);

    // weight packing
    pack_kernel<<<dim3(DMODEL / 128, DIN / 8, 1), 128>>>(w_in,  wp_in,  DIN, DMODEL);
    pack_kernel<<<dim3(DMODEL / 128, DMODEL / 8, 1), 128>>>(wv_sa, wp_vsa, DMODEL, DMODEL);
    pack_kernel<<<dim3(DMODEL / 128, DMODEL / 8, 1), 128>>>(wo_sa, wp_osa, DMODEL, DMODEL);
    pack_kernel<<<dim3(DMODEL / 128, DMODEL / 8, 1), 128>>>(wv_ca, wp_vca, DMODEL, DMODEL);
    pack_kernel<<<dim3(DMODEL / 128, DMODEL / 8, 1), 128>>>(wo_ca, wp_oca, DMODEL, DMODEL);
    pack_kernel<<<dim3(FDIM / 128, DMODEL / 8, 1), 128>>>(w_ff1, wp_ff1, DMODEL, FDIM);
    pack_kernel<<<dim3(DMODEL / 128, FDIM / 8, 1), 128>>>(w_ff2, wp_ff2, FDIM, DMODEL);
    pack_kernel<<<dim3(HD / 128, DMODEL / 8, NH), 128>>>(wh1, wp_h1, DMODEL, HD);
    pack_kernel<<<dim3(OUTD / 128, HD / 8, NH), 128>>>(wh2, wp_h2, HD, OUTD);

    dim3 blk(THREADS);
    const int MG = BATCH / BM;  // 64

    // 1) h = x @ w_in + b_in + pos   (h doubles as "mem")
    gemm_big<F_B2><<<dim3(DMODEL / BN, MG, 1), blk, SMB_BIG>>>(
        x, DIN, 0, wp_in, DMODEL, 0, h, DMODEL, 0, DIN, b_in, 0, pos, nullptr);

    // 2) t = ln1(h)
    ln_kernel<<<BATCH, 128>>>(h, t, ln1_g, ln1_b, DMODEL, 0);

    // 3) u = t @ wv_sa + bv_sa
    gemm_big<0><<<dim3(DMODEL / BN, MG, 1), blk, SMB_BIG>>>(
        t, DMODEL, 0, wp_vsa, DMODEL, 0, u, DMODEL, 0, DMODEL, bv_sa, 0, nullptr, nullptr);

    // 4) hb = h + u @ wo_sa + bo_sa
    gemm_big<F_RES><<<dim3(DMODEL / BN, MG, 1), blk, SMB_BIG>>>(
        u, DMODEL, 0, wp_osa, DMODEL, 0, hb, DMODEL, 0, DMODEL, bo_sa, 0, nullptr, h);

    // 5) t = h @ wv_ca + bv_ca   (h = pre-attn "mem")
    gemm_big<0><<<dim3(DMODEL / BN, MG, 1), blk, SMB_BIG>>>(
        h, DMODEL, 0, wp_vca, DMODEL, 0, t, DMODEL, 0, DMODEL, bv_ca, 0, nullptr, nullptr);

    // 6) h = hb + t @ wo_ca + bo_ca
    gemm_big<F_RES><<<dim3(DMODEL / BN, MG, 1), blk, SMB_BIG>>>(
        t, DMODEL, 0, wp_oca, DMODEL, 0, h, DMODEL, 0, DMODEL, bo_ca, 0, nullptr, hb);

    // 7) u = ln3(h)
    ln_kernel<<<BATCH, 128>>>(h, u, ln3_g, ln3_b, DMODEL, 0);

    // 8) ff = gelu(u @ w_ff1 + b_ff1)
    gemm_big<F_GELU><<<dim3(FDIM / BN, MG, 1), blk, SMB_BIG>>>(
        u, DMODEL, 0, wp_ff1, FDIM, 0, ff, FDIM, 0, DMODEL, b_ff1, 0, nullptr, nullptr);

    // 9) hb = h + ff @ w_ff2 + b_ff2
    gemm_big<F_RES><<<dim3(DMODEL / BN, MG, 1), blk, SMB_BIG>>>(
        ff, FDIM, 0, wp_ff2, DMODEL, 0, hb, DMODEL, 0, FDIM, b_ff2, 0, nullptr, h);

    // 10) t = lnout(hb)
    ln_kernel<<<BATCH, 128>>>(hb, t, lnout_g, lnout_b, DMODEL, 0);

    // 11) zz = gelu(t @ wh1 + bh1), batched over heads (N = 256 = one BN tile)
    gemm_big<F_GELU><<<dim3(HD / BN, MG, NH), blk, SMB_BIG>>>(
        t, DMODEL, 0, wp_h1, HD, (long)DMODEL * HD, zz, NH * HD, HD,
        DMODEL, bh1, HD, nullptr, nullptr);

    // 12) zz = ln_head(zz), per-head params, in place
    ln_kernel<<<BATCH * NH, 128>>>(zz, zz, lnh_g, lnh_b, HD, NH);

    // 13) out = zz @ wh2 + bh2, batched over heads (N=896 -> small kernel)
    gemm_sm<0><<<dim3(OUTD / SBN, MG, NH), blk, SMB_SM>>>(
        zz, NH * HD, HD, wp_h2, OUTD, (long)HD * OUTD, out, NH * OUTD, OUTD,
        HD, bh2, OUTD);
}